// round 1
// baseline (speedup 1.0000x reference)
#include <cuda_runtime.h>
#include <math.h>

#define NQ 8192
#define MK 8192
#define DD 128
#define BM 64
#define BN 64
#define NSPLIT 8
#define ROWS_PER_SPLIT (NQ / NSPLIT)   // 1024

// pad-68 float rows: 68*4=272 bytes, 16B aligned, conflict-free for float4 LDS
#define QK_STRIDE 68
#define V_STRIDE 132

__device__ float g_pmax[NSPLIT][MK];
__device__ float g_psum[NSPLIT][MK];
__device__ float g_cadj[MK];

// ---------------------------------------------------------------------------
// Kernel 1: per-column (key) partial softmax stats over a slice of queries.
// Each block: 64 key columns x 1024 query rows. Online max/sum across 16
// chunks of 64 rows. 4x4 register microtile per thread (16x16 threads).
// ---------------------------------------------------------------------------
__global__ __launch_bounds__(256, 1)
void colstats_kernel(const float* __restrict__ Q, const float* __restrict__ K) {
    extern __shared__ float sm[];
    float* Qs = sm;                   // [128][68] transposed: Qs[d][n]
    float* Ks = sm + DD * QK_STRIDE;  // [128][68] transposed: Ks[d][m]
    __shared__ float red[BM][17];
    __shared__ float runmax[BM];
    __shared__ float runsum[BM];
    __shared__ float newmax[BM];

    const int m0    = blockIdx.x * BM;
    const int nbase = blockIdx.y * ROWS_PER_SPLIT;
    const int tid   = threadIdx.x;
    const int tx    = tid & 15;
    const int ty    = tid >> 4;

    // Load K tile transposed (coalesced global reads)
    #pragma unroll
    for (int i = 0; i < (BM * DD) / 256; i++) {
        int idx = tid + i * 256;
        int m = idx >> 7;
        int d = idx & 127;
        Ks[d * QK_STRIDE + m] = K[(m0 + m) * DD + d];
    }
    if (tid < BM) { runmax[tid] = -1e30f; runsum[tid] = 0.0f; }

    for (int nc = 0; nc < ROWS_PER_SPLIT; nc += BN) {
        const int n0 = nbase + nc;
        __syncthreads();  // prior-iter readers done / K load visible
        #pragma unroll
        for (int i = 0; i < (BN * DD) / 256; i++) {
            int idx = tid + i * 256;
            int n = idx >> 7;
            int d = idx & 127;
            Qs[d * QK_STRIDE + n] = Q[(n0 + n) * DD + d];
        }
        __syncthreads();

        float acc[4][4];
        #pragma unroll
        for (int i = 0; i < 4; i++)
            #pragma unroll
            for (int j = 0; j < 4; j++) acc[i][j] = 0.0f;

        #pragma unroll 8
        for (int k = 0; k < DD; k++) {
            float4 a4 = *(const float4*)(Qs + k * QK_STRIDE + ty * 4);
            float4 b4 = *(const float4*)(Ks + k * QK_STRIDE + tx * 4);
            float av[4] = {a4.x, a4.y, a4.z, a4.w};
            float bv[4] = {b4.x, b4.y, b4.z, b4.w};
            #pragma unroll
            for (int i = 0; i < 4; i++)
                #pragma unroll
                for (int j = 0; j < 4; j++)
                    acc[i][j] += av[i] * bv[j];
        }

        // column-wise local max
        #pragma unroll
        for (int j = 0; j < 4; j++) {
            float mx = acc[0][j];
            #pragma unroll
            for (int i = 1; i < 4; i++) mx = fmaxf(mx, acc[i][j]);
            red[tx * 4 + j][ty] = mx;
        }
        __syncthreads();
        if (tid < BM) {
            float mx = red[tid][0];
            #pragma unroll
            for (int s = 1; s < 16; s++) mx = fmaxf(mx, red[tid][s]);
            float old = runmax[tid];
            float nm  = fmaxf(old, mx);
            newmax[tid] = nm;
            runsum[tid] *= __expf(old - nm);
            runmax[tid] = nm;
        }
        __syncthreads();
        // column-wise local sumexp against new max
        #pragma unroll
        for (int j = 0; j < 4; j++) {
            float nm = newmax[tx * 4 + j];
            float s = 0.0f;
            #pragma unroll
            for (int i = 0; i < 4; i++) s += __expf(acc[i][j] - nm);
            red[tx * 4 + j][ty] = s;
        }
        __syncthreads();
        if (tid < BM) {
            float s = 0.0f;
            #pragma unroll
            for (int k = 0; k < 16; k++) s += red[tid][k];
            runsum[tid] += s;
        }
    }
    __syncthreads();
    if (tid < BM) {
        g_pmax[blockIdx.y][m0 + tid] = runmax[tid];
        g_psum[blockIdx.y][m0 + tid] = runsum[tid];
    }
}

// ---------------------------------------------------------------------------
// Kernel 2: combine the NSPLIT partials into cadj[m] = max + log(sumexp)
// ---------------------------------------------------------------------------
__global__ void combine_kernel() {
    int m = blockIdx.x * blockDim.x + threadIdx.x;
    if (m >= MK) return;
    float gmax = -1e30f;
    #pragma unroll
    for (int s = 0; s < NSPLIT; s++) gmax = fmaxf(gmax, g_pmax[s][m]);
    float tot = 0.0f;
    #pragma unroll
    for (int s = 0; s < NSPLIT; s++)
        tot += g_psum[s][m] * __expf(g_pmax[s][m] - gmax);
    g_cadj[m] = gmax + __logf(tot);
}

// ---------------------------------------------------------------------------
// Kernel 3: out[n,:] = sum_m exp(Q[n]·K[m] - cadj[m]) * V[m,:]
// Each block: 64 query rows x full D=128 output, looping over key chunks.
// ---------------------------------------------------------------------------
__global__ __launch_bounds__(256, 1)
void out_kernel(const float* __restrict__ Q, const float* __restrict__ K,
                const float* __restrict__ V, float* __restrict__ out) {
    extern __shared__ float sm[];
    float* Qs = sm;                       // [128][68] Qs[d][n]
    float* Ks = Qs + DD * QK_STRIDE;      // [128][68] Ks[d][m]
    float* Vs = Ks + DD * QK_STRIDE;      // [64][132] Vs[m][d]
    float* Ps = Vs + BM * V_STRIDE;       // [64][68]  Ps[m][n]
    __shared__ float cadj_s[BM];

    const int n0  = blockIdx.x * BN;
    const int tid = threadIdx.x;
    const int tx  = tid & 15;
    const int ty  = tid >> 4;

    #pragma unroll
    for (int i = 0; i < (BN * DD) / 256; i++) {
        int idx = tid + i * 256;
        int n = idx >> 7;
        int d = idx & 127;
        Qs[d * QK_STRIDE + n] = Q[(n0 + n) * DD + d];
    }

    float oacc[4][8];
    #pragma unroll
    for (int i = 0; i < 4; i++)
        #pragma unroll
        for (int j = 0; j < 8; j++) oacc[i][j] = 0.0f;

    for (int mc = 0; mc < MK; mc += BM) {
        __syncthreads();  // prior-iter Ps/Vs readers done; Q load visible 1st iter
        #pragma unroll
        for (int i = 0; i < (BM * DD) / 256; i++) {
            int idx = tid + i * 256;
            int m = idx >> 7;
            int d = idx & 127;
            Ks[d * QK_STRIDE + m] = K[(mc + m) * DD + d];
            Vs[m * V_STRIDE + d]  = V[(mc + m) * DD + d];
        }
        if (tid < BM) cadj_s[tid] = g_cadj[mc + tid];
        __syncthreads();

        // QK^T 64x64 tile
        float acc[4][4];
        #pragma unroll
        for (int i = 0; i < 4; i++)
            #pragma unroll
            for (int j = 0; j < 4; j++) acc[i][j] = 0.0f;

        #pragma unroll 8
        for (int k = 0; k < DD; k++) {
            float4 a4 = *(const float4*)(Qs + k * QK_STRIDE + ty * 4);
            float4 b4 = *(const float4*)(Ks + k * QK_STRIDE + tx * 4);
            float av[4] = {a4.x, a4.y, a4.z, a4.w};
            float bv[4] = {b4.x, b4.y, b4.z, b4.w};
            #pragma unroll
            for (int i = 0; i < 4; i++)
                #pragma unroll
                for (int j = 0; j < 4; j++)
                    acc[i][j] += av[i] * bv[j];
        }

        // p = exp(s - cadj[m]), stored transposed Ps[m][n]
        #pragma unroll
        for (int j = 0; j < 4; j++) {
            float c = cadj_s[tx * 4 + j];
            #pragma unroll
            for (int i = 0; i < 4; i++)
                Ps[(tx * 4 + j) * QK_STRIDE + ty * 4 + i] = __expf(acc[i][j] - c);
        }
        __syncthreads();

        // PV: oacc[n=ty*4.., d=tx*8..] += P[n][m] * V[m][d]
        #pragma unroll 4
        for (int m = 0; m < BM; m++) {
            float4 p4 = *(const float4*)(Ps + m * QK_STRIDE + ty * 4);
            float pv[4] = {p4.x, p4.y, p4.z, p4.w};
            float4 v0 = *(const float4*)(Vs + m * V_STRIDE + tx * 8);
            float4 v1 = *(const float4*)(Vs + m * V_STRIDE + tx * 8 + 4);
            float vv[8] = {v0.x, v0.y, v0.z, v0.w, v1.x, v1.y, v1.z, v1.w};
            #pragma unroll
            for (int i = 0; i < 4; i++)
                #pragma unroll
                for (int d = 0; d < 8; d++)
                    oacc[i][d] += pv[i] * vv[d];
        }
    }

    #pragma unroll
    for (int i = 0; i < 4; i++) {
        int row = n0 + ty * 4 + i;
        float4 r0 = make_float4(oacc[i][0], oacc[i][1], oacc[i][2], oacc[i][3]);
        float4 r1 = make_float4(oacc[i][4], oacc[i][5], oacc[i][6], oacc[i][7]);
        *(float4*)(out + row * DD + tx * 8)     = r0;
        *(float4*)(out + row * DD + tx * 8 + 4) = r1;
    }
}

// ---------------------------------------------------------------------------
extern "C" void kernel_launch(void* const* d_in, const int* in_sizes, int n_in,
                              void* d_out, int out_size) {
    (void)in_sizes; (void)n_in; (void)out_size;
    const float* Q = (const float*)d_in[0];
    const float* K = (const float*)d_in[1];
    const float* V = (const float*)d_in[2];
    float* out = (float*)d_out;

    const size_t smemA = (size_t)(2 * DD * QK_STRIDE) * sizeof(float);            // 69,632 B
    const size_t smemC = (size_t)(2 * DD * QK_STRIDE + BM * V_STRIDE + BM * QK_STRIDE) * sizeof(float); // 120,832 B

    cudaFuncSetAttribute(colstats_kernel, cudaFuncAttributeMaxDynamicSharedMemorySize, (int)smemA);
    cudaFuncSetAttribute(out_kernel,      cudaFuncAttributeMaxDynamicSharedMemorySize, (int)smemC);

    colstats_kernel<<<dim3(MK / BM, NSPLIT), 256, smemA>>>(Q, K);
    combine_kernel<<<MK / 256, 256>>>();
    out_kernel<<<NQ / BN, 256, smemC>>>(Q, K, V, out);
}